// round 11
// baseline (speedup 1.0000x reference)
#include <cuda_runtime.h>
#include <cstdint>
#include <cfloat>

// Problem constants
#define N_TOTAL   32768
#define DIM       256
#define KCODES    1024
#define NTILES    512         // 64-row tiles, one CTA each (single wave at occ 4)
#define THREADS   256
#define CAP       24
#define EPSF      6e-3f      // >= 2x worst-case bf16 screening score error

#define QOUT_ELEMS   (32 * DIM * 32 * 32)
#define LOSS_ELEMS   N_TOTAL

// smem u32-word offsets
#define W_ZA      0           // 128 pair-rows * 64 = 8192 (bf16x2 z, swizzled)
#define W_WSB     8192        // 2 bufs * 16 e-rows * 128 = 4096
#define W_ROWMIN  12288       // 64
#define W_COUNT   12352       // 64
#define W_ROWIDX  12416       // 64
#define W_CAND    12480       // 64*24 = 1536
#define SMEM_WORDS 14016      // 56064 bytes -> 4 CTAs/SM

__device__ float    g_wsq[KCODES];
__device__ float    g_zsq[N_TOTAL];
__device__ uint32_t g_wpk[(DIM / 2) * KCODES];  // bf16x2 pairs (w[2e][c] lo, w[2e+1][c] hi)
__device__ float    g_wT[KCODES * DIM];         // transposed original w
__device__ float    g_zT[N_TOTAL * DIM];        // transposed original z

__device__ __forceinline__ uint32_t pack_bf16x2(float lo, float hi) {
    uint32_t r;
    asm("cvt.rn.bf16x2.f32 %0, %1, %2;" : "=r"(r) : "f"(hi), "f"(lo));
    return r;
}
__device__ __forceinline__ void mma_bf16(float* c, const uint32_t* a,
                                         uint32_t b0, uint32_t b1) {
    asm volatile(
        "mma.sync.aligned.m16n8k16.row.col.f32.bf16.bf16.f32 "
        "{%0,%1,%2,%3}, {%4,%5,%6,%7}, {%8,%9}, {%0,%1,%2,%3};"
        : "+f"(c[0]), "+f"(c[1]), "+f"(c[2]), "+f"(c[3])
        : "r"(a[0]), "r"(a[1]), "r"(a[2]), "r"(a[3]), "r"(b0), "r"(b1));
}
__device__ __forceinline__ uint32_t smem_u32(const void* p) {
    uint32_t a;
    asm("{ .reg .u64 t; cvta.to.shared.u64 t, %1; cvt.u32.u64 %0, t; }"
        : "=r"(a) : "l"(p));
    return a;
}
__device__ __forceinline__ void cp_async16(uint32_t dst, const void* src) {
    asm volatile("cp.async.ca.shared.global [%0], [%1], 16;"
                 :: "r"(dst), "l"(src) : "memory");
}
__device__ __forceinline__ void cp_async_commit() {
    asm volatile("cp.async.commit_group;" ::: "memory");
}
__device__ __forceinline__ void cp_async_wait0() {
    asm volatile("cp.async.wait_group 0;" ::: "memory");
}

// ---------------------------------------------------------------------------
// wsq[k] = sum_d w[d][k]^2
__global__ void __launch_bounds__(256)
wsq_kernel(const float* __restrict__ w) {
    __shared__ float red[8][32];
    const int tx = threadIdx.x, ty = threadIdx.y;
    const int k = blockIdx.x * 32 + tx;
    float s = 0.f;
#pragma unroll
    for (int i = 0; i < 32; i++) {
        float v = w[(size_t)(ty + 8 * i) * KCODES + k];
        s = __fadd_rn(s, __fmul_rn(v, v));
    }
    red[ty][tx] = s;
    __syncthreads();
    if (ty == 0) {
        float t = red[0][tx];
#pragma unroll
        for (int j = 1; j < 8; j++) t = __fadd_rn(t, red[j][tx]);
        g_wsq[k] = t;
    }
}

// w prep: g_wpk + g_wT
__global__ void __launch_bounds__(1024)
wprep_kernel(const float* __restrict__ w) {
    __shared__ float t[32][33];
    const int tx = threadIdx.x, ty = threadIdx.y;
    const int c0 = blockIdx.x * 32, d0 = blockIdx.y * 32;
    float v = w[(size_t)(d0 + ty) * KCODES + c0 + tx];
    t[ty][tx] = v;
    __syncthreads();
    g_wT[(size_t)(c0 + ty) * DIM + d0 + tx] = t[tx][ty];
    if (ty < 16) {
        const int e = (d0 >> 1) + ty;
        g_wpk[(size_t)e * KCODES + c0 + tx] = pack_bf16x2(t[2 * ty][tx], t[2 * ty + 1][tx]);
    }
}

// zsq[n] = sum_d z[n,d]^2  AND  g_zT[n][d] = z[d-major] transposed
__global__ void __launch_bounds__(1024)
zsq_kernel(const float* __restrict__ z) {
    __shared__ float sp[32][33];
    __shared__ float tr[32][33];
    const int tx = threadIdx.x, ty = threadIdx.y;
    const int n0 = blockIdx.x * 32;
    const int b  = n0 >> 10;
    const int hw = (n0 & 1023) + tx;
    const float* zb = z + ((size_t)(b * DIM) << 10) + hw;
    float p = 0.f;
#pragma unroll 1
    for (int i = 0; i < 8; i++) {
        float v = zb[(size_t)(ty + 32 * i) << 10];
        p = __fadd_rn(p, __fmul_rn(v, v));
        tr[ty][tx] = v;                 // d-lane ty, row tx
        __syncthreads();
        // warp ty writes row n0+ty, d = 32*i + tx (coalesced)
        g_zT[(size_t)(n0 + ty) * DIM + 32 * i + tx] = tr[tx][ty];
        __syncthreads();
    }
    sp[ty][tx] = p;
    __syncthreads();
    float val = sp[tx][ty];
#pragma unroll
    for (int off = 16; off >= 1; off >>= 1)
        val = __fadd_rn(val, __shfl_down_sync(0xffffffffu, val, off));
    if (tx == 0) g_zsq[n0 + ty] = val;
}

// ---------------------------------------------------------------------------
// Fused kernel: persistent-zA bf16 screening + conservative collect
//   + exact fp32 rescue argmin + gather + q_st + losses.  occ 4, single wave.
// ---------------------------------------------------------------------------
__global__ void __launch_bounds__(THREADS, 4)
vq_kernel(const float* __restrict__ z, const float* __restrict__ w,
          float* __restrict__ qout, float* __restrict__ loss,
          float* __restrict__ commit, float* __restrict__ embed) {
    extern __shared__ float sm[];
    uint32_t* zA      = (uint32_t*)sm + W_ZA;
    uint32_t* wsB     = (uint32_t*)sm + W_WSB;
    int*      srowmin = (int*)sm + W_ROWMIN;
    int*      scount  = (int*)sm + W_COUNT;
    int*      srowidx = (int*)sm + W_ROWIDX;
    int*      scand   = (int*)sm + W_CAND;
    float*    part    = (float*)scand;       // alias: epilogue only
    const uint32_t wsB_s = smem_u32(wsB);

    const int tid  = threadIdx.x;
    const int lane = tid & 31;
    const int warp = tid >> 5;
    const int wr = (warp & 1) * 32;
    const int wc = (warp >> 1) * 32;
    const int lg = lane >> 2;
    const int lt = lane & 3;

    const int n0  = blockIdx.x * 64;
    const int b   = n0 >> 10;
    const int hw0 = n0 & 1023;
    const float* zbase = z + ((size_t)(b * DIM) << 10) + hw0;

    // ---- build persistent zA (bf16x2, swizzled) ----
    {
        const int e  = tid >> 1;          // pair-row 0..127
        const int rh = tid & 1;
        const float* z0 = zbase + ((size_t)(2 * e) << 10) + rh * 32;
        const float* z1 = z0 + 1024;
        const uint32_t xorv = (uint32_t)((e & 3) << 3);
#pragma unroll
        for (int j = 0; j < 8; j++) {
            float4 x = *(const float4*)(z0 + j * 4);
            float4 y = *(const float4*)(z1 + j * 4);
            uint4 pk;
            pk.x = pack_bf16x2(x.x, y.x);
            pk.y = pack_bf16x2(x.y, y.y);
            pk.z = pack_bf16x2(x.z, y.z);
            pk.w = pack_bf16x2(x.w, y.w);
            *(uint4*)(zA + e * 64 + (((uint32_t)(rh * 32 + j * 4)) ^ xorv)) = pk;
        }
    }
    if (tid < 64) { srowmin[tid] = 0x7F7FFFFF; scount[tid] = 0; }

    // ---- prefetch W slab ss=0 (cp.async, buf 0) ----
    {
        const int e = tid >> 5, c16 = tid & 31;
        const uint32_t x0 = (uint32_t)((c16 * 4) ^ ((e & 3) << 3));
        cp_async16(wsB_s + 4u * (e * 128 + x0),
                   g_wpk + (size_t)e * KCODES + c16 * 4);
        cp_async16(wsB_s + 4u * ((e + 8) * 128 + (uint32_t)((c16 * 4) ^ (((e + 8) & 3) << 3))),
                   g_wpk + (size_t)(e + 8) * KCODES + c16 * 4);
        cp_async_commit();
        cp_async_wait0();
    }
    __syncthreads();

    float tzsq[4];
#pragma unroll
    for (int mi = 0; mi < 2; mi++)
#pragma unroll
        for (int h = 0; h < 2; h++)
            tzsq[mi * 2 + h] = __ldg(&g_zsq[n0 + wr + mi * 16 + h * 8 + lg]);

    // ---- screening over 8 k-tiles of 128 cols ----
    for (int kt = 0; kt < 8; kt++) {
        float acc[2][4][4];
#pragma unroll
        for (int mi = 0; mi < 2; mi++)
#pragma unroll
            for (int ni = 0; ni < 4; ni++)
#pragma unroll
                for (int q = 0; q < 4; q++) acc[mi][ni][q] = 0.f;

        for (int stage = 0; stage < 8; stage++) {
            const int ss = kt * 8 + stage;
            // prefetch ss+1 into the other buffer (zero-reg cp.async)
            if (ss < 63) {
                const int ssn = ss + 1;
                const int nkt = ssn >> 3, nst = ssn & 7;
                const uint32_t bo = (uint32_t)((ssn & 1) * 2048);
                const int e = tid >> 5, c16 = tid & 31;
                cp_async16(wsB_s + 4u * (bo + e * 128
                               + (uint32_t)((c16 * 4) ^ ((e & 3) << 3))),
                           g_wpk + (size_t)(nst * 16 + e) * KCODES
                               + nkt * 128 + c16 * 4);
                cp_async16(wsB_s + 4u * (bo + (e + 8) * 128
                               + (uint32_t)((c16 * 4) ^ (((e + 8) & 3) << 3))),
                           g_wpk + (size_t)(nst * 16 + e + 8) * KCODES
                               + nkt * 128 + c16 * 4);
                cp_async_commit();
            }

            // compute from buffer ss&1
            const uint32_t bufo = (uint32_t)((ss & 1) * 2048);
#pragma unroll
            for (int cc = 0; cc < 2; cc++) {
                const int er = stage * 16 + cc * 8 + lt;
                const uint32_t ax = (uint32_t)(lt << 3);
                uint32_t a[2][4];
#pragma unroll
                for (int mi = 0; mi < 2; mi++) {
                    const uint32_t r0 = (uint32_t)(wr + mi * 16 + lg);
                    a[mi][0] = zA[er * 64 + (r0 ^ ax)];
                    a[mi][1] = zA[er * 64 + ((r0 + 8) ^ ax)];
                    a[mi][2] = zA[(er + 4) * 64 + (r0 ^ ax)];
                    a[mi][3] = zA[(er + 4) * 64 + ((r0 + 8) ^ ax)];
                }
#pragma unroll
                for (int ni = 0; ni < 4; ni++) {
                    const uint32_t colx = (uint32_t)(wc + ni * 8 + lg) ^ ax;
                    uint32_t b0 = wsB[bufo + (cc * 8 + lt) * 128 + colx];
                    uint32_t b1 = wsB[bufo + (cc * 8 + lt + 4) * 128 + colx];
                    mma_bf16(acc[0][ni], a[0], b0, b1);
                    mma_bf16(acc[1][ni], a[1], b0, b1);
                }
            }
            cp_async_wait0();
            __syncthreads();
        }

        // pass 1: per-row screened running min (approx scores; EPS covers it)
#pragma unroll
        for (int mi = 0; mi < 2; mi++)
#pragma unroll
            for (int h = 0; h < 2; h++) {
                const int idx = mi * 2 + h;
                float rm = FLT_MAX;
#pragma unroll
                for (int ni = 0; ni < 4; ni++) {
                    const int col0 = kt * 128 + wc + ni * 8 + lt * 2;
                    float zw0 = __fadd_rn(tzsq[idx], __ldg(&g_wsq[col0]));
                    float zw1 = __fadd_rn(tzsq[idx], __ldg(&g_wsq[col0 + 1]));
                    float s0 = __fmaf_rn(-2.f, acc[mi][ni][h * 2], zw0);
                    float s1 = __fmaf_rn(-2.f, acc[mi][ni][h * 2 + 1], zw1);
                    rm = fminf(rm, fminf(s0, s1));
                }
                rm = fminf(rm, __shfl_xor_sync(0xffffffffu, rm, 1));
                rm = fminf(rm, __shfl_xor_sync(0xffffffffu, rm, 2));
                if (lt == 0)
                    atomicMin(&srowmin[wr + mi * 16 + h * 8 + lg],
                              __float_as_int(rm));
            }
        __syncthreads();

        // pass 2: collect candidates <= running row min + EPS (conservative)
#pragma unroll
        for (int mi = 0; mi < 2; mi++)
#pragma unroll
            for (int h = 0; h < 2; h++) {
                const int idx = mi * 2 + h;
                const int row = wr + mi * 16 + h * 8 + lg;
                const float thr = __int_as_float(srowmin[row]) + EPSF;
#pragma unroll
                for (int ni = 0; ni < 4; ni++) {
                    const int col0 = kt * 128 + wc + ni * 8 + lt * 2;
                    float zw0 = __fadd_rn(tzsq[idx], __ldg(&g_wsq[col0]));
                    float zw1 = __fadd_rn(tzsq[idx], __ldg(&g_wsq[col0 + 1]));
                    float s0 = __fmaf_rn(-2.f, acc[mi][ni][h * 2], zw0);
                    float s1 = __fmaf_rn(-2.f, acc[mi][ni][h * 2 + 1], zw1);
                    if (s0 <= thr) {
                        int p = atomicAdd(&scount[row], 1);
                        if (p < CAP) scand[row * CAP + p] = col0;
                    }
                    if (s1 <= thr) {
                        int p = atomicAdd(&scount[row], 1);
                        if (p < CAP) scand[row * CAP + p] = col0 + 1;
                    }
                }
            }
        // no sync needed: threshold monotonicity keeps collection conservative
    }
    __syncthreads();

    // ---- exact rescue: 4 threads/row, fp32 dots via g_zT/g_wT, exact bucketing ----
    {
        const int row = tid >> 2;
        const int t4  = tid & 3;
        const int cnt = scount[row];
        const float zsqr = __ldg(&g_zsq[n0 + row]);
        const float4* zp = (const float4*)(g_zT + (size_t)(n0 + row) * DIM);
        float bv = FLT_MAX;
        int   bi = 0x7FFFFFFF;

        auto exact_score = [&](int c) -> float {
            const float4* wp = (const float4*)(g_wT + (size_t)c * DIM);
            float a0 = 0.f, a1 = 0.f, a2 = 0.f, a3 = 0.f;
#pragma unroll 4
            for (int dq = 0; dq < DIM / 4; dq++) {
                float4 zv = __ldg(zp + dq);
                float4 wv = __ldg(wp + dq);
                a0 = __fmaf_rn(zv.x, wv.x, a0);
                a1 = __fmaf_rn(zv.y, wv.y, a1);
                a2 = __fmaf_rn(zv.z, wv.z, a2);
                a3 = __fmaf_rn(zv.w, wv.w, a3);
            }
            float dot = __fadd_rn(__fadd_rn(__fadd_rn(a0, a1), a2), a3);
            return __fsub_rn(__fadd_rn(zsqr, __ldg(&g_wsq[c])),
                             __fmul_rn(2.f, dot));
        };

        if (cnt <= CAP) {
            for (int i = t4; i < cnt; i += 4) {
                int c = scand[row * CAP + i];
                float s = exact_score(c);
                if (s < bv || (s == bv && c < bi)) { bv = s; bi = c; }
            }
        } else {  // overflow: deterministic full scan
            for (int c = t4; c < KCODES; c += 4) {
                float s = exact_score(c);
                if (s < bv || (s == bv && c < bi)) { bv = s; bi = c; }
            }
        }
#pragma unroll
        for (int off = 1; off <= 2; off <<= 1) {
            float v2 = __shfl_xor_sync(0xffffffffu, bv, off);
            int   i2 = __shfl_xor_sync(0xffffffffu, bi, off);
            if (v2 < bv || (v2 == bv && i2 < bi)) { bv = v2; bi = i2; }
        }
        if (t4 == 0) srowidx[row] = bi;
    }
    __syncthreads();

    // ---- epilogue: gather code, q_st, losses ----
    const int r  = tid & 63;
    const int dh = tid >> 6;    // 0..3
    const int kstar = srowidx[r];
    const float* wrow = g_wT + (size_t)kstar * DIM;
    float* qb = qout + ((size_t)(b * DIM) << 10) + hw0;
    float partial = 0.f;
#pragma unroll 4
    for (int d = dh; d < DIM; d += 4) {
        float wv = __ldg(wrow + d);
        float zv = __ldg(zbase + ((size_t)d << 10) + r);
        float diff = __fsub_rn(wv, zv);
        partial = __fmaf_rn(diff, diff, partial);
        qb[((size_t)d << 10) + r] = __fadd_rn(zv, diff);  // z + (q - z)
    }
    part[tid] = partial;
    __syncthreads();
    if (dh == 0) {
        float mse = __fmul_rn(
            __fadd_rn(__fadd_rn(part[r], part[64 + r]),
                      __fadd_rn(part[128 + r], part[192 + r])),
            1.0f / DIM);
        int n = n0 + r;
        commit[n] = mse;
        embed[n]  = mse;
        loss[n]   = __fadd_rn(__fmul_rn(0.25f, mse), mse);
    }
}

// ---------------------------------------------------------------------------
extern "C" void kernel_launch(void* const* d_in, const int* in_sizes, int n_in,
                              void* d_out, int out_size) {
    const float* z = (const float*)d_in[0];
    const float* w = (const float*)d_in[1];
    float* out    = (float*)d_out;
    float* qout   = out;
    float* loss   = out + QOUT_ELEMS;
    float* commit = loss + LOSS_ELEMS;
    float* embed  = commit + LOSS_ELEMS;

    wsq_kernel<<<KCODES / 32, dim3(32, 8)>>>(w);
    wprep_kernel<<<dim3(32, 8), dim3(32, 32)>>>(w);
    zsq_kernel<<<N_TOTAL / 32, dim3(32, 32)>>>(z);

    const size_t smem_bytes = SMEM_WORDS * sizeof(float);
    static bool attr_set = false;
    if (!attr_set) {
        cudaFuncSetAttribute(vq_kernel, cudaFuncAttributeMaxDynamicSharedMemorySize,
                             (int)smem_bytes);
        attr_set = true;
    }
    vq_kernel<<<NTILES, THREADS, smem_bytes>>>(z, w, qout, loss, commit, embed);
}

// round 12
// speedup vs baseline: 1.0170x; 1.0170x over previous
#include <cuda_runtime.h>
#include <cstdint>
#include <cfloat>

// Problem constants
#define N_TOTAL   32768
#define DIM       256
#define KCODES    1024
#define NTILES    512         // 64-row tiles
#define THREADS   256
#define GRID_VQ   444         // 148 SMs * 3 CTAs, persistent work-stealing
#define CAP       24
#define EPSF      6e-3f       // >= 2x worst-case bf16 screening score error

#define QOUT_ELEMS   (32 * DIM * 32 * 32)
#define LOSS_ELEMS   N_TOTAL

// smem u32-word offsets
#define W_ZA      0           // 128 pair-rows * 64 = 8192 (bf16x2 z, swizzled)
#define W_WSB     8192        // 3 bufs * 16 e-rows * 128 = 6144
#define W_ROWMIN  14336       // 64
#define W_COUNT   14400       // 64
#define W_ROWIDX  14464       // 64
#define W_TILE    14528       // 4 (counter broadcast + pad)
#define W_CAND    14532       // 64*24 = 1536
#define SMEM_WORDS 16068      // 64272 bytes -> 3 CTAs/SM

__device__ float    g_wsq[KCODES];
__device__ float    g_zsq[N_TOTAL];
__device__ uint32_t g_wpk[(DIM / 2) * KCODES];  // bf16x2 pairs (w[2e][c] lo, w[2e+1][c] hi)
__device__ float    g_wT[KCODES * DIM];         // transposed original w
__device__ float    g_zT[N_TOTAL * DIM];        // transposed original z
__device__ int      g_tile_ctr;

__device__ __forceinline__ uint32_t pack_bf16x2(float lo, float hi) {
    uint32_t r;
    asm("cvt.rn.bf16x2.f32 %0, %1, %2;" : "=r"(r) : "f"(hi), "f"(lo));
    return r;
}
__device__ __forceinline__ void mma_bf16(float* c, const uint32_t* a,
                                         uint32_t b0, uint32_t b1) {
    asm volatile(
        "mma.sync.aligned.m16n8k16.row.col.f32.bf16.bf16.f32 "
        "{%0,%1,%2,%3}, {%4,%5,%6,%7}, {%8,%9}, {%0,%1,%2,%3};"
        : "+f"(c[0]), "+f"(c[1]), "+f"(c[2]), "+f"(c[3])
        : "r"(a[0]), "r"(a[1]), "r"(a[2]), "r"(a[3]), "r"(b0), "r"(b1));
}
__device__ __forceinline__ uint32_t smem_u32(const void* p) {
    uint32_t a;
    asm("{ .reg .u64 t; cvta.to.shared.u64 t, %1; cvt.u32.u64 %0, t; }"
        : "=r"(a) : "l"(p));
    return a;
}
__device__ __forceinline__ void cp_async16(uint32_t dst, const void* src) {
    asm volatile("cp.async.ca.shared.global [%0], [%1], 16;"
                 :: "r"(dst), "l"(src) : "memory");
}
__device__ __forceinline__ void cp_async_commit() {
    asm volatile("cp.async.commit_group;" ::: "memory");
}
__device__ __forceinline__ void cp_async_wait1() {
    asm volatile("cp.async.wait_group 1;" ::: "memory");
}
__device__ __forceinline__ void cp_async_wait0() {
    asm volatile("cp.async.wait_group 0;" ::: "memory");
}

// ---------------------------------------------------------------------------
__global__ void reset_ctr_kernel() { g_tile_ctr = 0; }

// wsq[k] = sum_d w[d][k]^2
__global__ void __launch_bounds__(256)
wsq_kernel(const float* __restrict__ w) {
    __shared__ float red[8][32];
    const int tx = threadIdx.x, ty = threadIdx.y;
    const int k = blockIdx.x * 32 + tx;
    float s = 0.f;
#pragma unroll
    for (int i = 0; i < 32; i++) {
        float v = w[(size_t)(ty + 8 * i) * KCODES + k];
        s = __fadd_rn(s, __fmul_rn(v, v));
    }
    red[ty][tx] = s;
    __syncthreads();
    if (ty == 0) {
        float t = red[0][tx];
#pragma unroll
        for (int j = 1; j < 8; j++) t = __fadd_rn(t, red[j][tx]);
        g_wsq[k] = t;
    }
}

// w prep: g_wpk + g_wT
__global__ void __launch_bounds__(1024)
wprep_kernel(const float* __restrict__ w) {
    __shared__ float t[32][33];
    const int tx = threadIdx.x, ty = threadIdx.y;
    const int c0 = blockIdx.x * 32, d0 = blockIdx.y * 32;
    float v = w[(size_t)(d0 + ty) * KCODES + c0 + tx];
    t[ty][tx] = v;
    __syncthreads();
    g_wT[(size_t)(c0 + ty) * DIM + d0 + tx] = t[tx][ty];
    if (ty < 16) {
        const int e = (d0 >> 1) + ty;
        g_wpk[(size_t)e * KCODES + c0 + tx] = pack_bf16x2(t[2 * ty][tx], t[2 * ty + 1][tx]);
    }
}

// zsq[n] = sum_d z[n,d]^2  AND  g_zT[n][d] = transposed z
__global__ void __launch_bounds__(1024)
zsq_kernel(const float* __restrict__ z) {
    __shared__ float sp[32][33];
    __shared__ float tr[32][33];
    const int tx = threadIdx.x, ty = threadIdx.y;
    const int n0 = blockIdx.x * 32;
    const int b  = n0 >> 10;
    const int hw = (n0 & 1023) + tx;
    const float* zb = z + ((size_t)(b * DIM) << 10) + hw;
    float p = 0.f;
#pragma unroll 1
    for (int i = 0; i < 8; i++) {
        float v = zb[(size_t)(ty + 32 * i) << 10];
        p = __fadd_rn(p, __fmul_rn(v, v));
        tr[ty][tx] = v;
        __syncthreads();
        g_zT[(size_t)(n0 + ty) * DIM + 32 * i + tx] = tr[tx][ty];
        __syncthreads();
    }
    sp[ty][tx] = p;
    __syncthreads();
    float val = sp[tx][ty];
#pragma unroll
    for (int off = 16; off >= 1; off >>= 1)
        val = __fadd_rn(val, __shfl_down_sync(0xffffffffu, val, off));
    if (tx == 0) g_zsq[n0 + ty] = val;
}

// ---------------------------------------------------------------------------
// Persistent fused kernel: persistent-zA bf16 screening + conservative collect
//   + exact fp32 rescue argmin + gather + q_st + losses.  occ 3.
// ---------------------------------------------------------------------------
__global__ void __launch_bounds__(THREADS, 3)
vq_kernel(const float* __restrict__ z, const float* __restrict__ w,
          float* __restrict__ qout, float* __restrict__ loss,
          float* __restrict__ commit, float* __restrict__ embed) {
    extern __shared__ float sm[];
    uint32_t* zA      = (uint32_t*)sm + W_ZA;
    uint32_t* wsB     = (uint32_t*)sm + W_WSB;
    int*      srowmin = (int*)sm + W_ROWMIN;
    int*      scount  = (int*)sm + W_COUNT;
    int*      srowidx = (int*)sm + W_ROWIDX;
    int*      stile   = (int*)sm + W_TILE;
    int*      scand   = (int*)sm + W_CAND;
    float*    part    = (float*)scand;       // alias: epilogue only
    const uint32_t wsB_s = smem_u32(wsB);

    const int tid  = threadIdx.x;
    const int lane = tid & 31;
    const int warp = tid >> 5;
    const int wr = (warp & 1) * 32;
    const int wc = (warp >> 1) * 32;
    const int lg = lane >> 2;
    const int lt = lane & 3;

    for (;;) {
        if (tid == 0) stile[0] = atomicAdd(&g_tile_ctr, 1);
        __syncthreads();
        const int tile = stile[0];
        if (tile >= NTILES) break;

        const int n0  = tile * 64;
        const int b   = n0 >> 10;
        const int hw0 = n0 & 1023;
        const float* zbase = z + ((size_t)(b * DIM) << 10) + hw0;

        // ---- build persistent zA (bf16x2, XOR-swizzled) ----
        {
            const int e  = tid >> 1;          // pair-row 0..127
            const int rh = tid & 1;
            const float* z0 = zbase + ((size_t)(2 * e) << 10) + rh * 32;
            const float* z1 = z0 + 1024;
            const uint32_t xorv = (uint32_t)((e & 3) << 3);
#pragma unroll
            for (int j = 0; j < 8; j++) {
                float4 x = *(const float4*)(z0 + j * 4);
                float4 y = *(const float4*)(z1 + j * 4);
                uint4 pk;
                pk.x = pack_bf16x2(x.x, y.x);
                pk.y = pack_bf16x2(x.y, y.y);
                pk.z = pack_bf16x2(x.z, y.z);
                pk.w = pack_bf16x2(x.w, y.w);
                *(uint4*)(zA + e * 64 + (((uint32_t)(rh * 32 + j * 4)) ^ xorv)) = pk;
            }
        }
        if (tid < 64) { srowmin[tid] = 0x7F7FFFFF; scount[tid] = 0; }

        // ---- prefetch W slab ss=0 into buf 0 ----
        {
            const int e = tid >> 5, c16 = tid & 31;
            cp_async16(wsB_s + 4u * (e * 128
                           + (uint32_t)((c16 * 4) ^ ((e & 3) << 3))),
                       g_wpk + (size_t)e * KCODES + c16 * 4);
            cp_async16(wsB_s + 4u * ((e + 8) * 128
                           + (uint32_t)((c16 * 4) ^ (((e + 8) & 3) << 3))),
                       g_wpk + (size_t)(e + 8) * KCODES + c16 * 4);
            cp_async_commit();
        }

        float tzsq[4];
#pragma unroll
        for (int mi = 0; mi < 2; mi++)
#pragma unroll
            for (int h = 0; h < 2; h++)
                tzsq[mi * 2 + h] = __ldg(&g_zsq[n0 + wr + mi * 16 + h * 8 + lg]);

        // ---- screening over 8 k-tiles of 128 cols ----
        for (int kt = 0; kt < 8; kt++) {
            float acc[2][4][4];
#pragma unroll
            for (int mi = 0; mi < 2; mi++)
#pragma unroll
                for (int ni = 0; ni < 4; ni++)
#pragma unroll
                    for (int q = 0; q < 4; q++) acc[mi][ni][q] = 0.f;

            for (int stage = 0; stage < 8; stage++) {
                const int ss = kt * 8 + stage;
                // prefetch ss+1 into buf (ss+1)%3 (zero-reg cp.async)
                if (ss < 63) {
                    const int ssn = ss + 1;
                    const int nkt = ssn >> 3, nst = ssn & 7;
                    const uint32_t bo = (uint32_t)((ssn % 3) * 2048);
                    const int e = tid >> 5, c16 = tid & 31;
                    cp_async16(wsB_s + 4u * (bo + e * 128
                                   + (uint32_t)((c16 * 4) ^ ((e & 3) << 3))),
                               g_wpk + (size_t)(nst * 16 + e) * KCODES
                                   + nkt * 128 + c16 * 4);
                    cp_async16(wsB_s + 4u * (bo + (e + 8) * 128
                                   + (uint32_t)((c16 * 4) ^ (((e + 8) & 3) << 3))),
                               g_wpk + (size_t)(nst * 16 + e + 8) * KCODES
                                   + nkt * 128 + c16 * 4);
                    cp_async_commit();
                    cp_async_wait1();   // slab ss complete; ss+1 still in flight
                } else {
                    cp_async_wait0();
                }
                __syncthreads();        // slab ss visible to all warps

                // compute from buffer ss%3
                const uint32_t bufo = (uint32_t)((ss % 3) * 2048);
#pragma unroll
                for (int cc = 0; cc < 2; cc++) {
                    const int er = stage * 16 + cc * 8 + lt;
                    const uint32_t ax = (uint32_t)(lt << 3);
                    uint32_t a[2][4];
#pragma unroll
                    for (int mi = 0; mi < 2; mi++) {
                        const uint32_t r0 = (uint32_t)(wr + mi * 16 + lg);
                        a[mi][0] = zA[er * 64 + (r0 ^ ax)];
                        a[mi][1] = zA[er * 64 + ((r0 + 8) ^ ax)];
                        a[mi][2] = zA[(er + 4) * 64 + (r0 ^ ax)];
                        a[mi][3] = zA[(er + 4) * 64 + ((r0 + 8) ^ ax)];
                    }
#pragma unroll
                    for (int ni = 0; ni < 4; ni++) {
                        const uint32_t colx = (uint32_t)(wc + ni * 8 + lg) ^ ax;
                        uint32_t b0 = wsB[bufo + (cc * 8 + lt) * 128 + colx];
                        uint32_t b1 = wsB[bufo + (cc * 8 + lt + 4) * 128 + colx];
                        mma_bf16(acc[0][ni], a[0], b0, b1);
                        mma_bf16(acc[1][ni], a[1], b0, b1);
                    }
                }
                // no trailing sync: next iteration's barrier provides the
                // WAR ordering for buffer reuse at distance 3.
            }

            // pass 1: per-row screened running min
#pragma unroll
            for (int mi = 0; mi < 2; mi++)
#pragma unroll
                for (int h = 0; h < 2; h++) {
                    const int idx = mi * 2 + h;
                    float rm = FLT_MAX;
#pragma unroll
                    for (int ni = 0; ni < 4; ni++) {
                        const int col0 = kt * 128 + wc + ni * 8 + lt * 2;
                        float zw0 = __fadd_rn(tzsq[idx], __ldg(&g_wsq[col0]));
                        float zw1 = __fadd_rn(tzsq[idx], __ldg(&g_wsq[col0 + 1]));
                        float s0 = __fmaf_rn(-2.f, acc[mi][ni][h * 2], zw0);
                        float s1 = __fmaf_rn(-2.f, acc[mi][ni][h * 2 + 1], zw1);
                        rm = fminf(rm, fminf(s0, s1));
                    }
                    rm = fminf(rm, __shfl_xor_sync(0xffffffffu, rm, 1));
                    rm = fminf(rm, __shfl_xor_sync(0xffffffffu, rm, 2));
                    if (lt == 0)
                        atomicMin(&srowmin[wr + mi * 16 + h * 8 + lg],
                                  __float_as_int(rm));
                }
            __syncthreads();

            // pass 2: collect candidates <= running row min + EPS
#pragma unroll
            for (int mi = 0; mi < 2; mi++)
#pragma unroll
                for (int h = 0; h < 2; h++) {
                    const int idx = mi * 2 + h;
                    const int row = wr + mi * 16 + h * 8 + lg;
                    const float thr = __int_as_float(srowmin[row]) + EPSF;
#pragma unroll
                    for (int ni = 0; ni < 4; ni++) {
                        const int col0 = kt * 128 + wc + ni * 8 + lt * 2;
                        float zw0 = __fadd_rn(tzsq[idx], __ldg(&g_wsq[col0]));
                        float zw1 = __fadd_rn(tzsq[idx], __ldg(&g_wsq[col0 + 1]));
                        float s0 = __fmaf_rn(-2.f, acc[mi][ni][h * 2], zw0);
                        float s1 = __fmaf_rn(-2.f, acc[mi][ni][h * 2 + 1], zw1);
                        if (s0 <= thr) {
                            int p = atomicAdd(&scount[row], 1);
                            if (p < CAP) scand[row * CAP + p] = col0;
                        }
                        if (s1 <= thr) {
                            int p = atomicAdd(&scount[row], 1);
                            if (p < CAP) scand[row * CAP + p] = col0 + 1;
                        }
                    }
                }
            // no sync: threshold monotonicity keeps collection conservative
        }
        __syncthreads();

        // ---- exact rescue: 4 threads/row, fp32 via g_zT/g_wT, exact bucketing ----
        {
            const int row = tid >> 2;
            const int t4  = tid & 3;
            const int cnt = scount[row];
            const float zsqr = __ldg(&g_zsq[n0 + row]);
            const float4* zp = (const float4*)(g_zT + (size_t)(n0 + row) * DIM);
            float bv = FLT_MAX;
            int   bi = 0x7FFFFFFF;

            auto exact_score = [&](int c) -> float {
                const float4* wp = (const float4*)(g_wT + (size_t)c * DIM);
                float a0 = 0.f, a1 = 0.f, a2 = 0.f, a3 = 0.f;
#pragma unroll 4
                for (int dq = 0; dq < DIM / 4; dq++) {
                    float4 zv = __ldg(zp + dq);
                    float4 wv = __ldg(wp + dq);
                    a0 = __fmaf_rn(zv.x, wv.x, a0);
                    a1 = __fmaf_rn(zv.y, wv.y, a1);
                    a2 = __fmaf_rn(zv.z, wv.z, a2);
                    a3 = __fmaf_rn(zv.w, wv.w, a3);
                }
                float dot = __fadd_rn(__fadd_rn(__fadd_rn(a0, a1), a2), a3);
                return __fsub_rn(__fadd_rn(zsqr, __ldg(&g_wsq[c])),
                                 __fmul_rn(2.f, dot));
            };

            if (cnt <= CAP) {
                for (int i = t4; i < cnt; i += 4) {
                    int c = scand[row * CAP + i];
                    float s = exact_score(c);
                    if (s < bv || (s == bv && c < bi)) { bv = s; bi = c; }
                }
            } else {  // overflow: deterministic full scan
                for (int c = t4; c < KCODES; c += 4) {
                    float s = exact_score(c);
                    if (s < bv || (s == bv && c < bi)) { bv = s; bi = c; }
                }
            }
#pragma unroll
            for (int off = 1; off <= 2; off <<= 1) {
                float v2 = __shfl_xor_sync(0xffffffffu, bv, off);
                int   i2 = __shfl_xor_sync(0xffffffffu, bi, off);
                if (v2 < bv || (v2 == bv && i2 < bi)) { bv = v2; bi = i2; }
            }
            if (t4 == 0) srowidx[row] = bi;
        }
        __syncthreads();

        // ---- epilogue: gather code, q_st, losses ----
        const int r  = tid & 63;
        const int dh = tid >> 6;    // 0..3
        const int kstar = srowidx[r];
        const float* wrow = g_wT + (size_t)kstar * DIM;
        float* qb = qout + ((size_t)(b * DIM) << 10) + hw0;
        float partial = 0.f;
#pragma unroll 4
        for (int d = dh; d < DIM; d += 4) {
            float wv = __ldg(wrow + d);
            float zv = __ldg(zbase + ((size_t)d << 10) + r);
            float diff = __fsub_rn(wv, zv);
            partial = __fmaf_rn(diff, diff, partial);
            qb[((size_t)d << 10) + r] = __fadd_rn(zv, diff);  // z + (q - z)
        }
        part[tid] = partial;
        __syncthreads();
        if (dh == 0) {
            float mse = __fmul_rn(
                __fadd_rn(__fadd_rn(part[r], part[64 + r]),
                          __fadd_rn(part[128 + r], part[192 + r])),
                1.0f / DIM);
            int n = n0 + r;
            commit[n] = mse;
            embed[n]  = mse;
            loss[n]   = __fadd_rn(__fmul_rn(0.25f, mse), mse);
        }
        __syncthreads();   // smem reuse barrier before next tile
    }
}

// ---------------------------------------------------------------------------
extern "C" void kernel_launch(void* const* d_in, const int* in_sizes, int n_in,
                              void* d_out, int out_size) {
    const float* z = (const float*)d_in[0];
    const float* w = (const float*)d_in[1];
    float* out    = (float*)d_out;
    float* qout   = out;
    float* loss   = out + QOUT_ELEMS;
    float* commit = loss + LOSS_ELEMS;
    float* embed  = commit + LOSS_ELEMS;

    reset_ctr_kernel<<<1, 1>>>();
    wsq_kernel<<<KCODES / 32, dim3(32, 8)>>>(w);
    wprep_kernel<<<dim3(32, 8), dim3(32, 32)>>>(w);
    zsq_kernel<<<N_TOTAL / 32, dim3(32, 32)>>>(z);

    const size_t smem_bytes = SMEM_WORDS * sizeof(float);
    static bool attr_set = false;
    if (!attr_set) {
        cudaFuncSetAttribute(vq_kernel, cudaFuncAttributeMaxDynamicSharedMemorySize,
                             (int)smem_bytes);
        attr_set = true;
    }
    vq_kernel<<<GRID_VQ, THREADS, smem_bytes>>>(z, w, qout, loss, commit, embed);
}

// round 13
// speedup vs baseline: 4.4806x; 4.4056x over previous
#include <cuda_runtime.h>
#include <cstdint>
#include <cfloat>

// Problem constants
#define N_TOTAL   32768
#define DIM       256
#define KCODES    1024
#define NTILES    512         // 64-row tiles
#define THREADS   256
#define GRID_VQ   296         // 148 SMs * 2 CTAs (occupancy-2 persistent grid)
#define ZSTR      72          // zs row stride (floats) >= 64; 72 % 32 == 8
#define CAP       32
#define EPSF      6e-3f       // >= 2x worst-case bf16 screening score error

#define QOUT_ELEMS   (32 * DIM * 32 * 32)
#define LOSS_ELEMS   N_TOTAL

// smem word offsets (identical to the 250us R10 kernel)
#define W_ZS      0           // 256*72 = 18432
#define W_ZA      18432       // 16 rows * 72 = 1152 (bf16x2 fragments of z)
#define W_WSB     19584       // 16 rows * 136 = 2176 (bf16x2 codebook slab)
#define W_ROWMIN  21760       // 64
#define W_COUNT   21824       // 64
#define W_ROWIDX  21888       // 64
#define W_TILE    21952       // 1 (+pad)
#define W_CAND    21956       // 64*32 = 2048
#define SMEM_WORDS 24004      // 96016 bytes -> 2 CTAs/SM

__device__ float    g_wsq[KCODES];
__device__ float    g_zsq[N_TOTAL];
__device__ uint32_t g_wpk[(DIM / 2) * KCODES];  // bf16x2 pairs (w[2e][c] lo, w[2e+1][c] hi)
__device__ float    g_wT[KCODES * DIM];         // transposed original w
__device__ int      g_tile_ctr;

__device__ __forceinline__ uint32_t pack_bf16x2(float lo, float hi) {
    uint32_t r;
    asm("cvt.rn.bf16x2.f32 %0, %1, %2;" : "=r"(r) : "f"(hi), "f"(lo));
    return r;
}
// m16n8k16 bf16 mma: D = A*B + D (fp32 accum)
__device__ __forceinline__ void mma_bf16(float* c, const uint32_t* a,
                                         uint32_t b0, uint32_t b1) {
    asm volatile(
        "mma.sync.aligned.m16n8k16.row.col.f32.bf16.bf16.f32 "
        "{%0,%1,%2,%3}, {%4,%5,%6,%7}, {%8,%9}, {%0,%1,%2,%3};"
        : "+f"(c[0]), "+f"(c[1]), "+f"(c[2]), "+f"(c[3])
        : "r"(a[0]), "r"(a[1]), "r"(a[2]), "r"(a[3]), "r"(b0), "r"(b1));
}

// ---------------------------------------------------------------------------
__global__ void reset_ctr_kernel() { g_tile_ctr = 0; }

// wsq[k] = sum_d w[d][k]^2
__global__ void __launch_bounds__(256)
wsq_kernel(const float* __restrict__ w) {
    __shared__ float red[8][32];
    const int tx = threadIdx.x, ty = threadIdx.y;
    const int k = blockIdx.x * 32 + tx;
    float s = 0.f;
#pragma unroll
    for (int i = 0; i < 32; i++) {
        float v = w[(size_t)(ty + 8 * i) * KCODES + k];
        s = __fadd_rn(s, __fmul_rn(v, v));
    }
    red[ty][tx] = s;
    __syncthreads();
    if (ty == 0) {
        float t = red[0][tx];
#pragma unroll
        for (int j = 1; j < 8; j++) t = __fadd_rn(t, red[j][tx]);
        g_wsq[k] = t;
    }
}

// w prep: g_wpk (bf16x2 d-pairs) + g_wT (transpose)
__global__ void __launch_bounds__(1024)
wprep_kernel(const float* __restrict__ w) {
    __shared__ float t[32][33];
    const int tx = threadIdx.x, ty = threadIdx.y;
    const int c0 = blockIdx.x * 32, d0 = blockIdx.y * 32;
    float v = w[(size_t)(d0 + ty) * KCODES + c0 + tx];
    t[ty][tx] = v;
    __syncthreads();
    g_wT[(size_t)(c0 + ty) * DIM + d0 + tx] = t[tx][ty];
    if (ty < 16) {
        const int e = (d0 >> 1) + ty;
        g_wpk[(size_t)e * KCODES + c0 + tx] = pack_bf16x2(t[2 * ty][tx], t[2 * ty + 1][tx]);
    }
}

// zsq[n] = sum_d z[n,d]^2 (fast R10 version, no transpose)
__global__ void __launch_bounds__(1024)
zsq_kernel(const float* __restrict__ z) {
    __shared__ float sp[32][33];
    const int tx = threadIdx.x, ty = threadIdx.y;
    const int n0 = blockIdx.x * 32;
    const int b  = n0 >> 10;
    const int hw = (n0 & 1023) + tx;
    const float* zb = z + ((size_t)(b * DIM) << 10) + hw;
    float p = 0.f;
#pragma unroll
    for (int i = 0; i < 8; i++) {
        float v = zb[(size_t)(ty + 32 * i) << 10];
        p = __fadd_rn(p, __fmul_rn(v, v));
    }
    sp[ty][tx] = p;
    __syncthreads();
    float val = sp[tx][ty];
#pragma unroll
    for (int off = 16; off >= 1; off >>= 1)
        val = __fadd_rn(val, __shfl_down_sync(0xffffffffu, val, off));
    if (tx == 0) g_zsq[n0 + ty] = val;
}

// ---------------------------------------------------------------------------
// Persistent fused kernel (R10 structure): bf16 screening GEMM with
// register-prefetched W slabs + conservative collect + exact fp32 rescue
// argmin + gather + q_st + losses.
// ---------------------------------------------------------------------------
__global__ void __launch_bounds__(THREADS, 2)
vq_kernel(const float* __restrict__ z, const float* __restrict__ w,
          float* __restrict__ qout, float* __restrict__ loss,
          float* __restrict__ commit, float* __restrict__ embed) {
    extern __shared__ float sm[];
    float*    zs      = sm + W_ZS;
    uint32_t* zA      = (uint32_t*)(sm + W_ZA);
    uint32_t* wsB     = (uint32_t*)(sm + W_WSB);
    int*      srowmin = (int*)(sm + W_ROWMIN);
    int*      scount  = (int*)(sm + W_COUNT);
    int*      srowidx = (int*)(sm + W_ROWIDX);
    int*      stile   = (int*)(sm + W_TILE);
    int*      scand   = (int*)(sm + W_CAND);
    float*    part    = (float*)scand;          // alias: epilogue only

    const int tid  = threadIdx.x;
    const int warp = tid >> 5;
    const int lane = tid & 31;
    const int wr = (warp & 1) * 32;
    const int wc = (warp >> 1) * 32;
    const int lg = lane >> 2;
    const int lt = lane & 3;

    // staging indices for the W slab (identical to R10's copy loop)
    const int we0 = tid >> 5;          // j=0: e = 0..7
    const int wc16 = tid & 31;

    for (;;) {
        if (tid == 0) stile[0] = atomicAdd(&g_tile_ctr, 1);
        __syncthreads();
        const int tile = stile[0];
        if (tile >= NTILES) break;

        const int n0  = tile * 64;
        const int b   = n0 >> 10;
        const int hw0 = n0 & 1023;
        const float* zbase = z + ((size_t)(b * DIM) << 10) + hw0;

        // ---- load z tile (fp32, kept for rescue/epilogue) ----
        for (int i = tid; i < DIM * 16; i += THREADS) {
            int d = i >> 4, f = i & 15;
            *(float4*)(zs + d * ZSTR + f * 4) =
                *(const float4*)(zbase + ((size_t)d << 10) + f * 4);
        }
        if (tid < 64) { srowmin[tid] = 0x7F7FFFFF; scount[tid] = 0; }

        // ---- preload W slab ss=0 into registers ----
        uint4 wpre0 = *(const uint4*)(g_wpk + (size_t)we0 * KCODES + wc16 * 4);
        uint4 wpre1 = *(const uint4*)(g_wpk + (size_t)(we0 + 8) * KCODES + wc16 * 4);

        float tzsq[4];
#pragma unroll
        for (int mi = 0; mi < 2; mi++)
#pragma unroll
            for (int h = 0; h < 2; h++)
                tzsq[mi * 2 + h] = __ldg(&g_zsq[n0 + wr + mi * 16 + h * 8 + lg]);

        // ---- screening: 8 k-tiles of 128 codebook cols ----
        for (int kt = 0; kt < 8; kt++) {
            float acc[2][4][4];
#pragma unroll
            for (int mi = 0; mi < 2; mi++)
#pragma unroll
                for (int ni = 0; ni < 4; ni++)
#pragma unroll
                    for (int q = 0; q < 4; q++) acc[mi][ni][q] = 0.f;

            for (int stage = 0; stage < 8; stage++) {
                const int ss = kt * 8 + stage;
                __syncthreads();   // prior readers of zA/wsB done (covers zs 1st)

                // store the register-held slab ss into wsB
                *(uint4*)(wsB + we0 * 136 + wc16 * 4) = wpre0;
                *(uint4*)(wsB + (we0 + 8) * 136 + wc16 * 4) = wpre1;

                // stage zA: bf16x2 fragment layout, 2 tasks/thread (from zs)
#pragma unroll
                for (int j = 0; j < 2; j++) {
                    const int p = tid + j * 256;
                    const int r = p & 63, plt = (p >> 6) & 3, pcc = p >> 8;
                    const int d0 = stage * 32 + pcc * 16 + plt * 2;
                    float z0 = zs[d0 * ZSTR + r];
                    float z1 = zs[(d0 + 1) * ZSTR + r];
                    float z2 = zs[(d0 + 8) * ZSTR + r];
                    float z3 = zs[(d0 + 9) * ZSTR + r];
                    zA[(pcc * 4 + plt) * 72 + r]       = pack_bf16x2(z0, z1);
                    zA[(8 + pcc * 4 + plt) * 72 + r]   = pack_bf16x2(z2, z3);
                }
                __syncthreads();

                // prefetch slab ss+1 into registers (overlaps with the MMAs)
                if (ss < 63) {
                    const int ssn = ss + 1;
                    const int nkt = ssn >> 3, nst = ssn & 7;
                    wpre0 = *(const uint4*)(g_wpk
                        + (size_t)(nst * 16 + we0) * KCODES + nkt * 128 + wc16 * 4);
                    wpre1 = *(const uint4*)(g_wpk
                        + (size_t)(nst * 16 + we0 + 8) * KCODES + nkt * 128 + wc16 * 4);
                }

                // compute: 2 k16-chunks, 2 mtiles x 4 ntiles
#pragma unroll
                for (int cc = 0; cc < 2; cc++) {
                    uint32_t a[2][4];
#pragma unroll
                    for (int mi = 0; mi < 2; mi++) {
                        const int r0 = wr + mi * 16 + lg;
                        const int rlo = (cc * 4 + lt) * 72;
                        const int rhi = rlo + 8 * 72;
                        a[mi][0] = zA[rlo + r0];
                        a[mi][1] = zA[rlo + r0 + 8];
                        a[mi][2] = zA[rhi + r0];
                        a[mi][3] = zA[rhi + r0 + 8];
                    }
#pragma unroll
                    for (int ni = 0; ni < 4; ni++) {
                        const int col = wc + ni * 8 + lg;
                        uint32_t b0 = wsB[(cc * 8 + lt) * 136 + col];
                        uint32_t b1 = wsB[(cc * 8 + lt + 4) * 136 + col];
                        mma_bf16(acc[0][ni], a[0], b0, b1);
                        mma_bf16(acc[1][ni], a[1], b0, b1);
                    }
                }
            }

            // pass 1: per-row screened running min
#pragma unroll
            for (int mi = 0; mi < 2; mi++)
#pragma unroll
                for (int h = 0; h < 2; h++) {
                    const int idx = mi * 2 + h;
                    float rm = FLT_MAX;
#pragma unroll
                    for (int ni = 0; ni < 4; ni++) {
                        const int col0 = kt * 128 + wc + ni * 8 + lt * 2;
                        float s0 = __fsub_rn(__fadd_rn(tzsq[idx], __ldg(&g_wsq[col0])),
                                             __fmul_rn(2.f, acc[mi][ni][h * 2]));
                        float s1 = __fsub_rn(__fadd_rn(tzsq[idx], __ldg(&g_wsq[col0 + 1])),
                                             __fmul_rn(2.f, acc[mi][ni][h * 2 + 1]));
                        rm = fminf(rm, fminf(s0, s1));
                    }
                    rm = fminf(rm, __shfl_xor_sync(0xffffffffu, rm, 1));
                    rm = fminf(rm, __shfl_xor_sync(0xffffffffu, rm, 2));
                    if (lt == 0)
                        atomicMin(&srowmin[wr + mi * 16 + h * 8 + lg],
                                  __float_as_int(rm));
                }
            __syncthreads();

            // pass 2: collect candidates <= running row min + EPS (conservative)
#pragma unroll
            for (int mi = 0; mi < 2; mi++)
#pragma unroll
                for (int h = 0; h < 2; h++) {
                    const int idx = mi * 2 + h;
                    const int row = wr + mi * 16 + h * 8 + lg;
                    const float thr = __int_as_float(srowmin[row]) + EPSF;
#pragma unroll
                    for (int ni = 0; ni < 4; ni++) {
                        const int col0 = kt * 128 + wc + ni * 8 + lt * 2;
                        float s0 = __fsub_rn(__fadd_rn(tzsq[idx], __ldg(&g_wsq[col0])),
                                             __fmul_rn(2.f, acc[mi][ni][h * 2]));
                        float s1 = __fsub_rn(__fadd_rn(tzsq[idx], __ldg(&g_wsq[col0 + 1])),
                                             __fmul_rn(2.f, acc[mi][ni][h * 2 + 1]));
                        if (s0 <= thr) {
                            int p = atomicAdd(&scount[row], 1);
                            if (p < CAP) scand[row * CAP + p] = col0;
                        }
                        if (s1 <= thr) {
                            int p = atomicAdd(&scount[row], 1);
                            if (p < CAP) scand[row * CAP + p] = col0 + 1;
                        }
                    }
                }
        }
        __syncthreads();

        // ---- exact rescue: 4 threads per row, fp32, exact bucketing ----
        {
            const int row = tid >> 2;
            const int t4  = tid & 3;
            const int cnt = scount[row];
            const float zsqr = __ldg(&g_zsq[n0 + row]);
            float bv = FLT_MAX;
            int   bi = 0x7FFFFFFF;

            auto exact_score = [&](int c) -> float {
                const float4* wp = (const float4*)(g_wT + (size_t)c * DIM);
                float a0 = 0.f, a1 = 0.f, a2 = 0.f, a3 = 0.f;
#pragma unroll 8
                for (int dq = 0; dq < DIM / 4; dq++) {
                    float4 wv = __ldg(wp + dq);
                    const int d = dq * 4;
                    a0 = __fmaf_rn(zs[d * ZSTR + row], wv.x, a0);
                    a1 = __fmaf_rn(zs[(d + 1) * ZSTR + row], wv.y, a1);
                    a2 = __fmaf_rn(zs[(d + 2) * ZSTR + row], wv.z, a2);
                    a3 = __fmaf_rn(zs[(d + 3) * ZSTR + row], wv.w, a3);
                }
                float dot = __fadd_rn(__fadd_rn(__fadd_rn(a0, a1), a2), a3);
                return __fsub_rn(__fadd_rn(zsqr, __ldg(&g_wsq[c])),
                                 __fmul_rn(2.f, dot));
            };

            if (cnt <= CAP) {
                for (int i = t4; i < cnt; i += 4) {
                    int c = scand[row * CAP + i];
                    float s = exact_score(c);
                    if (s < bv || (s == bv && c < bi)) { bv = s; bi = c; }
                }
            } else {  // overflow: deterministic full scan
                for (int c = t4; c < KCODES; c += 4) {
                    float s = exact_score(c);
                    if (s < bv || (s == bv && c < bi)) { bv = s; bi = c; }
                }
            }
#pragma unroll
            for (int off = 1; off <= 2; off <<= 1) {
                float v2 = __shfl_xor_sync(0xffffffffu, bv, off);
                int   i2 = __shfl_xor_sync(0xffffffffu, bi, off);
                if (v2 < bv || (v2 == bv && i2 < bi)) { bv = v2; bi = i2; }
            }
            if (t4 == 0) srowidx[row] = bi;
        }
        __syncthreads();

        // ---- epilogue: gather code, q_st, losses ----
        const int r  = tid & 63;
        const int dh = tid >> 6;    // 0..3
        const int kstar = srowidx[r];
        const float* wrow = g_wT + (size_t)kstar * DIM;
        float* qb = qout + ((size_t)(b * DIM) << 10) + hw0;
        float partial = 0.f;
#pragma unroll 4
        for (int d = dh; d < DIM; d += 4) {
            float wv = __ldg(wrow + d);
            float zv = zs[d * ZSTR + r];
            float diff = __fsub_rn(wv, zv);
            partial = __fmaf_rn(diff, diff, partial);
            qb[((size_t)d << 10) + r] = __fadd_rn(zv, diff);  // z + (q - z)
        }
        part[tid] = partial;
        __syncthreads();
        if (dh == 0) {
            float mse = __fmul_rn(
                __fadd_rn(__fadd_rn(part[r], part[64 + r]),
                          __fadd_rn(part[128 + r], part[192 + r])),
                1.0f / DIM);
            int n = n0 + r;
            commit[n] = mse;
            embed[n]  = mse;
            loss[n]   = __fadd_rn(__fmul_rn(0.25f, mse), mse);
        }
        __syncthreads();   // smem reuse barrier before next tile
    }
}

// ---------------------------------------------------------------------------
extern "C" void kernel_launch(void* const* d_in, const int* in_sizes, int n_in,
                              void* d_out, int out_size) {
    const float* z = (const float*)d_in[0];
    const float* w = (const float*)d_in[1];
    float* out    = (float*)d_out;
    float* qout   = out;
    float* loss   = out + QOUT_ELEMS;
    float* commit = loss + LOSS_ELEMS;
    float* embed  = commit + LOSS_ELEMS;

    reset_ctr_kernel<<<1, 1>>>();
    wsq_kernel<<<KCODES / 32, dim3(32, 8)>>>(w);
    wprep_kernel<<<dim3(32, 8), dim3(32, 32)>>>(w);
    zsq_kernel<<<N_TOTAL / 32, dim3(32, 32)>>>(z);

    const size_t smem_bytes = SMEM_WORDS * sizeof(float);
    static bool attr_set = false;
    if (!attr_set) {
        cudaFuncSetAttribute(vq_kernel, cudaFuncAttributeMaxDynamicSharedMemorySize,
                             (int)smem_bytes);
        attr_set = true;
    }
    vq_kernel<<<GRID_VQ, THREADS, smem_bytes>>>(z, w, qout, loss, commit, embed);
}